// round 12
// baseline (speedup 1.0000x reference)
#include <cuda_runtime.h>
#include <cstdint>

// PoolingLayer: out[i, :] = max_{k<32} features[nbr[i,k], :]
// N=100000 input rows, N'=50000 output rows, K=32 neighbors, F=128 float32.
// Inputs: points (100000x3 f32, UNUSED), features (100000x128 f32),
//         neighbor_indices (50000x32, stored as INT32 — JAX w/o x64 downcasts
//         int64 to int32; reading as int64 caused the round-6 addr-space trap).
// Output: 50000x128 f32.

#define NP    50000
#define KNBR  32
#define FDIM  128
#define F4    (FDIM / 4)   // 32 float4 per row -> one per lane

__device__ __forceinline__ float4 fmax4(float4 a, float4 b) {
    a.x = fmaxf(a.x, b.x);
    a.y = fmaxf(a.y, b.y);
    a.z = fmaxf(a.z, b.z);
    a.w = fmaxf(a.w, b.w);
    return a;
}

__global__ __launch_bounds__(256) void pool_max_kernel(
    const float4* __restrict__ feat,   // [N, 32] float4 view of [N,128] f32
    const int* __restrict__ nbr,       // [NP, 32] int32
    float4* __restrict__ out)          // [NP, 32] float4 view
{
    const int gtid = blockIdx.x * blockDim.x + threadIdx.x;
    const int row  = gtid >> 5;        // one warp per output row
    const int lane = gtid & 31;
    if (row >= NP) return;

    // Each lane loads its own neighbor index (coalesced 4B load),
    // then indices are broadcast across the warp with shuffles.
    const int my_idx = nbr[row * KNBR + lane];

    // Initialize with neighbor 0's row.
    int id0 = __shfl_sync(0xffffffffu, my_idx, 0);
    float4 m = feat[id0 * F4 + lane];

    // Remaining 31 neighbors, batched 8 at a time for MLP:
    // k = 1..7 (partial batch), then 8..31 in batches of 8.
    float4 v[8];
    #pragma unroll
    for (int j = 0; j < 7; ++j) {
        int id = __shfl_sync(0xffffffffu, my_idx, 1 + j);
        v[j] = feat[id * F4 + lane];
    }
    #pragma unroll
    for (int j = 0; j < 7; ++j) m = fmax4(m, v[j]);

    #pragma unroll
    for (int k = 8; k < KNBR; k += 8) {
        #pragma unroll
        for (int j = 0; j < 8; ++j) {
            int id = __shfl_sync(0xffffffffu, my_idx, k + j);
            v[j] = feat[id * F4 + lane];
        }
        #pragma unroll
        for (int j = 0; j < 8; ++j) m = fmax4(m, v[j]);
    }

    out[row * F4 + lane] = m;
}

extern "C" void kernel_launch(void* const* d_in, const int* in_sizes, int n_in,
                              void* d_out, int out_size)
{
    // Identify inputs by element count (robust to metadata ordering):
    //   points           : 100000*3   =   300000
    //   features         : 100000*128 = 12800000
    //   neighbor_indices : 50000*32   =  1600000
    const float4* feat = nullptr;
    const int*    nbr  = nullptr;
    for (int i = 0; i < n_in; ++i) {
        if (in_sizes[i] == 12800000)      feat = (const float4*)d_in[i];
        else if (in_sizes[i] == 1600000)  nbr  = (const int*)d_in[i];
    }
    // Fallback to documented order if sizes ever change.
    if (!feat) feat = (const float4*)d_in[1];
    if (!nbr)  nbr  = (const int*)d_in[2];

    float4* out = (float4*)d_out;

    const int total_threads = NP * 32;           // one warp per row
    const int block = 256;
    const int grid  = (total_threads + block - 1) / block;  // 6250
    pool_max_kernel<<<grid, block>>>(feat, nbr, out);
}

// round 16
// speedup vs baseline: 1.0312x; 1.0312x over previous
#include <cuda_runtime.h>
#include <cstdint>

// PoolingLayer: out[i, :] = max_{k<32} features[nbr[i,k], :]
// N=100000 input rows, N'=50000 output rows, K=32 neighbors, F=128 float32.
// Inputs: points (unused), features (100000x128 f32), neighbor_indices
// (50000x32 int32 on device). Output: 50000x128 f32.
//
// R12 profile: 45.5us, L2=72.7%, DRAM=20.2%, occ=67.9% (38 regs -> 6 CTA/SM).
// R13 change: batch 8->4 + __launch_bounds__(256,8) to hit 8 CTA/SM (100% occ).
// More warps (not more per-warp MLP) is what pushes L2 toward its cap.

#define NP    50000
#define KNBR  32
#define FDIM  128
#define F4    (FDIM / 4)   // 32 float4 per row -> one per lane

__device__ __forceinline__ float4 fmax4(float4 a, float4 b) {
    a.x = fmaxf(a.x, b.x);
    a.y = fmaxf(a.y, b.y);
    a.z = fmaxf(a.z, b.z);
    a.w = fmaxf(a.w, b.w);
    return a;
}

__global__ __launch_bounds__(256, 8) void pool_max_kernel(
    const float4* __restrict__ feat,   // [N, 32] float4 view of [N,128] f32
    const int* __restrict__ nbr,       // [NP, 32] int32
    float4* __restrict__ out)          // [NP, 32] float4 view
{
    const int gtid = blockIdx.x * blockDim.x + threadIdx.x;
    const int row  = gtid >> 5;        // one warp per output row
    const int lane = gtid & 31;
    if (row >= NP) return;

    // Each lane loads its own neighbor index (coalesced 4B load),
    // then indices are broadcast across the warp with shuffles.
    const int my_idx = nbr[row * KNBR + lane];

    float4 v[4];

    // First batch: neighbors 0..3. Init m from v[0].
    #pragma unroll
    for (int j = 0; j < 4; ++j) {
        int id = __shfl_sync(0xffffffffu, my_idx, j);
        v[j] = feat[id * F4 + lane];
    }
    float4 m = v[0];
    m = fmax4(m, v[1]);
    m = fmax4(m, v[2]);
    m = fmax4(m, v[3]);

    // Remaining neighbors in batches of 4 (16 live regs for the batch;
    // total ~28-30 regs -> 8 CTAs/SM under launch_bounds(256,8)).
    #pragma unroll
    for (int k = 4; k < KNBR; k += 4) {
        #pragma unroll
        for (int j = 0; j < 4; ++j) {
            int id = __shfl_sync(0xffffffffu, my_idx, k + j);
            v[j] = feat[id * F4 + lane];
        }
        m = fmax4(m, v[0]);
        m = fmax4(m, v[1]);
        m = fmax4(m, v[2]);
        m = fmax4(m, v[3]);
    }

    out[row * F4 + lane] = m;
}

extern "C" void kernel_launch(void* const* d_in, const int* in_sizes, int n_in,
                              void* d_out, int out_size)
{
    // Identify inputs by element count (robust to metadata ordering):
    //   points           : 100000*3   =   300000
    //   features         : 100000*128 = 12800000
    //   neighbor_indices : 50000*32   =  1600000
    const float4* feat = nullptr;
    const int*    nbr  = nullptr;
    for (int i = 0; i < n_in; ++i) {
        if (in_sizes[i] == 12800000)      feat = (const float4*)d_in[i];
        else if (in_sizes[i] == 1600000)  nbr  = (const int*)d_in[i];
    }
    // Fallback to documented order if sizes ever change.
    if (!feat) feat = (const float4*)d_in[1];
    if (!nbr)  nbr  = (const int*)d_in[2];

    float4* out = (float4*)d_out;

    const int total_threads = NP * 32;           // one warp per row
    const int block = 256;
    const int grid  = (total_threads + block - 1) / block;  // 6250
    pool_max_kernel<<<grid, block>>>(feat, nbr, out);
}